// round 17
// baseline (speedup 1.0000x reference)
#include <cuda_runtime.h>
#include <cuda_bf16.h>
#include <math.h>
#include <stdint.h>

#define NB 8192
#define ND 256
#define BM 128
#define BN 128
#define NTILE 64            // NB/BM
#define NBLK 2080           // NTILE*(NTILE+1)/2
#define RSB 512             // row_stats blocks (16 rows each)
#define GRID 148            // persistent CTAs

// exp(sim/T) = exp2(sim * (log2e / T))
#define CEXP 20.6099291551f

// ---------------- scratch (no allocations allowed) ----------------
__device__ uint8_t g_f8[NB * ND];          // normalized features, e4m3 (2 MB)
__device__ float  g_dsq[NB];
__device__ float  g_accL0[NB];
__device__ float  g_accT[NB];
__device__ double p_sum[RSB], p_ssq[RSB], p_ctr[RSB];
__device__ int    p_cnt[RSB];
__device__ double g_center_d, g_mc_d;
__device__ float  g_m;
__device__ int    g_cnt;
__device__ unsigned g_tick_rs, g_tick_cf;

// ---------------- helpers ----------------
__device__ __forceinline__ uint32_t smem_u32(const void* p) {
    uint32_t a;
    asm("{ .reg .u64 t; cvta.to.shared.u64 t, %1; cvt.u32.u64 %0, t; }" : "=r"(a) : "l"(p));
    return a;
}
__device__ __forceinline__ float ex2f(float x) {
    float y; asm("ex2.approx.ftz.f32 %0, %1;" : "=f"(y) : "f"(x)); return y;
}
__device__ __forceinline__ void cp_async16(uint32_t s, const void* g) {
    asm volatile("cp.async.cg.shared.global [%0], [%1], 16;" :: "r"(s), "l"(g));
}
__device__ __forceinline__ void ldsm_x4(uint32_t* r, uint32_t addr) {
    asm volatile("ldmatrix.sync.aligned.m8n8.x4.shared.b16 {%0,%1,%2,%3}, [%4];"
                 : "=r"(r[0]), "=r"(r[1]), "=r"(r[2]), "=r"(r[3]) : "r"(addr));
}
__device__ __forceinline__ void mma16832(float* c, const uint32_t* a,
                                         uint32_t b0, uint32_t b1) {
    asm volatile("mma.sync.aligned.m16n8k32.row.col.f32.e4m3.e4m3.f32 "
                 "{%0,%1,%2,%3}, {%4,%5,%6,%7}, {%8,%9}, {%0,%1,%2,%3};"
                 : "+f"(c[0]), "+f"(c[1]), "+f"(c[2]), "+f"(c[3])
                 : "r"(a[0]), "r"(a[1]), "r"(a[2]), "r"(a[3]), "r"(b0), "r"(b1));
}
__device__ __forceinline__ uint32_t pack_e4m3_4(float v0, float v1, float v2, float v3) {
    uint16_t lo, hi;
    asm("cvt.rn.satfinite.e4m3x2.f32 %0, %1, %2;" : "=h"(lo) : "f"(v1), "f"(v0));
    asm("cvt.rn.satfinite.e4m3x2.f32 %0, %1, %2;" : "=h"(hi) : "f"(v3), "f"(v2));
    return (uint32_t)lo | ((uint32_t)hi << 16);
}
__device__ __forceinline__ void tile_ij(int u, int& ti, int& tj) {
    int t = (int)((129.0 - sqrt(129.0 * 129.0 - 8.0 * (double)u)) * 0.5);
    int base = t * NTILE - (t * (t - 1)) / 2;
    if (u < base) { t--; base = t * NTILE - (t * (t - 1)) / 2; }
    else if (u >= base + (NTILE - t)) { t++; base = t * NTILE - (t * (t - 1)) / 2; }
    ti = t; tj = t + (u - base);
}

// ---------------- pass 1: stats + e4m3 normalize (2 rows/warp) ----------------
__global__ void row_stats(const float* __restrict__ feat,
                          const int*   __restrict__ lab,
                          const float* __restrict__ cen,
                          const float* __restrict__ rsig) {
    __shared__ double sh_sm[8], sh_ssq[8], sh_ctr[8];
    __shared__ int    sh_cnt[8];
    __shared__ int    s_last;
    const int wrp  = threadIdx.x >> 5;
    const int lane = threadIdx.x & 31;
    const int row0 = blockIdx.x * 16 + wrp * 2;

    const float4* cr = (const float4*)cen;
    float4 cv0 = cr[lane], cv1 = cr[32 + lane];

    float4 x[2][2];
#pragma unroll
    for (int r = 0; r < 2; r++) {
        const float4* fr = (const float4*)(feat + (size_t)(row0 + r) * ND);
        x[r][0] = fr[lane];
        x[r][1] = fr[32 + lane];
    }

    double wsum = 0.0, wssq = 0.0, wctr = 0.0;
    int    wcnt = 0;
#pragma unroll
    for (int r = 0; r < 2; r++) {
        int row = row0 + r;
        float dsq = 0.f, ssq = 0.f, sm = 0.f;
#pragma unroll
        for (int c = 0; c < 2; c++) {
            float4 v = x[r][c], cv = c ? cv1 : cv0;
            float dx = v.x - cv.x, dy = v.y - cv.y, dz = v.z - cv.z, dw = v.w - cv.w;
            dsq += dx*dx + dy*dy + dz*dz + dw*dw;
            ssq += v.x*v.x + v.y*v.y + v.z*v.z + v.w*v.w;
            sm  += v.x + v.y + v.z + v.w;
        }
#pragma unroll
        for (int o = 16; o > 0; o >>= 1) {
            dsq += __shfl_xor_sync(0xffffffffu, dsq, o);
            ssq += __shfl_xor_sync(0xffffffffu, ssq, o);
            sm  += __shfl_xor_sync(0xffffffffu, sm , o);
        }
        float inv_norm = 1.f / fmaxf(sqrtf(ssq), 1e-12f);
#pragma unroll
        for (int c = 0; c < 2; c++) {
            float4 v = x[r][c];
            int d0 = (c * 32 + lane) * 4;
            uint32_t w = pack_e4m3_4(v.x*inv_norm, v.y*inv_norm,
                                     v.z*inv_norm, v.w*inv_norm);
            *(uint32_t*)&g_f8[(size_t)row * ND + d0] = w;
        }
        if (lane == 0) {
            g_dsq[row] = dsq;
            g_accL0[row] = 0.f;
            g_accT[row]  = 0.f;
            if (lab[row] == 0) {
                wsum += (double)sm; wssq += (double)ssq;
                wctr += (double)dsq; wcnt++;
            }
        }
    }
    if (lane == 0) {
        sh_sm[wrp] = wsum; sh_ssq[wrp] = wssq; sh_ctr[wrp] = wctr; sh_cnt[wrp] = wcnt;
    }
    __syncthreads();
    if (threadIdx.x == 0) {
        double a = 0, b2 = 0, c2 = 0; int n = 0;
#pragma unroll
        for (int w = 0; w < 8; w++) { a += sh_sm[w]; b2 += sh_ssq[w]; c2 += sh_ctr[w]; n += sh_cnt[w]; }
        p_sum[blockIdx.x] = a; p_ssq[blockIdx.x] = b2;
        p_ctr[blockIdx.x] = c2; p_cnt[blockIdx.x] = n;
        __threadfence();
        unsigned t = atomicAdd(&g_tick_rs, 1u);
        s_last = (t == RSB - 1);
    }
    __syncthreads();

    if (s_last) {
        __shared__ double r0[256], r1[256], r2[256];
        __shared__ int    r3[256];
        int t = threadIdx.x;
        double a = 0, b = 0, c = 0; int n = 0;
#pragma unroll
        for (int q = 0; q < RSB / 256; q++) {
            int idx = t + q * 256;
            a += p_sum[idx]; b += p_ssq[idx]; c += p_ctr[idx]; n += p_cnt[idx];
        }
        r0[t] = a; r1[t] = b; r2[t] = c; r3[t] = n;
        __syncthreads();
        for (int o = 128; o > 0; o >>= 1) {
            if (t < o) { r0[t] += r0[t+o]; r1[t] += r1[t+o]; r2[t] += r2[t+o]; r3[t] += r3[t+o]; }
            __syncthreads();
        }
        if (t == 0) {
            int cnt = r3[0];
            double n_el  = (double)cnt * (double)ND;
            double var   = (r1[0] - r0[0] * r0[0] / n_el) / (n_el - 1.0);
            double sigma = 0.9 * (double)rsig[0] + 0.1 * sqrt(var);
            g_m = (float)(0.5 + 0.3 * sigma + 0.3 * (1.0 - 224.0 / 900.0));
            g_center_d = r2[0];
            g_cnt = cnt;
            g_mc_d = 0.0;
            g_tick_rs = 0u;
        }
    }
}

// ---------------- pass 2: persistent pipelined FP8 contrastive ----------------
__shared__ float s_w0c[3][BN];
__shared__ float s_w0r[3][BM];

// epilogue chunk fn of previous tile (E regs): row sums into racc, col sums flushed
__device__ __forceinline__ void epi_chunk(
    int fn, const float (&E)[2][8][4], float (&racc)[8],
    int pslot, int pj0, int pr_base, int pdiag,
    int wn, int rl, int lane)
{
    int jl = wn * 64 + fn * 8 + (lane & 3) * 2;
    float w0a = s_w0c[pslot][jl], w0b = s_w0c[pslot][jl + 1];
    if (!pdiag) {
        float cTa = 0.f, cTb = 0.f, c0a = 0.f, c0b = 0.f;
#pragma unroll
        for (int fm = 0; fm < 2; fm++) {
            float e00 = ex2f(E[fm][fn][0] * CEXP);
            float e01 = ex2f(E[fm][fn][1] * CEXP);
            float e10 = ex2f(E[fm][fn][2] * CEXP);
            float e11 = ex2f(E[fm][fn][3] * CEXP);
            racc[fm*4+0] = fmaf(e00, w0a, fmaf(e01, w0b, racc[fm*4+0]));
            racc[fm*4+1] += e00 + e01;
            racc[fm*4+2] = fmaf(e10, w0a, fmaf(e11, w0b, racc[fm*4+2]));
            racc[fm*4+3] += e10 + e11;
            float wrA = s_w0r[pslot][rl + fm * 16];
            float wrB = s_w0r[pslot][rl + fm * 16 + 8];
            cTa += e00 + e10; cTb += e01 + e11;
            c0a = fmaf(e00, wrA, fmaf(e10, wrB, c0a));
            c0b = fmaf(e01, wrA, fmaf(e11, wrB, c0b));
        }
#pragma unroll
        for (int o = 4; o <= 16; o <<= 1) {
            cTa += __shfl_xor_sync(0xffffffffu, cTa, o);
            cTb += __shfl_xor_sync(0xffffffffu, cTb, o);
            c0a += __shfl_xor_sync(0xffffffffu, c0a, o);
            c0b += __shfl_xor_sync(0xffffffffu, c0b, o);
        }
        if ((lane >> 2) == 0) {
            int jc = pj0 + wn * 64 + fn * 8 + lane * 2;
            atomicAdd(&g_accT[jc],      cTa);
            atomicAdd(&g_accT[jc + 1],  cTb);
            atomicAdd(&g_accL0[jc],     c0a);
            atomicAdd(&g_accL0[jc + 1], c0b);
        }
    } else {
        int jg = pj0 + jl;
#pragma unroll
        for (int fm = 0; fm < 2; fm++) {
            int r0 = pr_base + fm * 16, r1 = r0 + 8;
            float e00 = ex2f(E[fm][fn][0] * CEXP);
            float e01 = ex2f(E[fm][fn][1] * CEXP);
            float e10 = ex2f(E[fm][fn][2] * CEXP);
            float e11 = ex2f(E[fm][fn][3] * CEXP);
            if (r0 == jg)     e00 = 0.f;
            if (r0 == jg + 1) e01 = 0.f;
            if (r1 == jg)     e10 = 0.f;
            if (r1 == jg + 1) e11 = 0.f;
            racc[fm*4+0] = fmaf(e00, w0a, fmaf(e01, w0b, racc[fm*4+0]));
            racc[fm*4+1] += e00 + e01;
            racc[fm*4+2] = fmaf(e10, w0a, fmaf(e11, w0b, racc[fm*4+2]));
            racc[fm*4+3] += e10 + e11;
        }
    }
}

__device__ __forceinline__ void flush_racc(float (&racc)[8], int pr_base, int lane) {
#pragma unroll
    for (int o = 1; o < 4; o <<= 1)
#pragma unroll
        for (int q = 0; q < 8; q++)
            racc[q] += __shfl_xor_sync(0xffffffffu, racc[q], o);
    if ((lane & 3) == 0) {
#pragma unroll
        for (int fm = 0; fm < 2; fm++) {
            int r0 = pr_base + fm * 16, r1 = r0 + 8;
            atomicAdd(&g_accL0[r0], racc[fm*4+0]);
            atomicAdd(&g_accT[r0],  racc[fm*4+1]);
            atomicAdd(&g_accL0[r1], racc[fm*4+2]);
            atomicAdd(&g_accT[r1],  racc[fm*4+3]);
        }
    }
}

__global__ void __launch_bounds__(256, 1) contrast_mma(const int* __restrict__ lab) {
    extern __shared__ __align__(16) char dsm[];   // 2 tile buffers x 64KB
    const uint32_t sbase = smem_u32(dsm);
    const int tid = threadIdx.x, lane = tid & 31, wid = tid >> 5;
    const int wm = wid & 3, wn = wid >> 2;
    const int rl = wm * 32 + (lane >> 2);

    const int cnt = (NBLK - 1 - (int)blockIdx.x) / GRID + 1;

    // prefetch tile for iteration "it" into buffer it&1, labels slot it%3
    auto prefetch_tile = [&](int it) {
        int u = blockIdx.x + it * GRID;
        int ti, tj; tile_ij(u, ti, tj);
        int i0 = ti * BM, j0 = tj * BN;
        uint32_t tb = sbase + (uint32_t)(it & 1) * 65536u;
#pragma unroll
        for (int kb = 0; kb < 2; kb++) {
            uint32_t a_s = tb + (uint32_t)kb * 32768u;
            uint32_t b_s = a_s + 16384u;
            const uint8_t* gA = g_f8 + (size_t)i0 * ND + kb * 128;
            const uint8_t* gB = g_f8 + (size_t)j0 * ND + kb * 128;
#pragma unroll
            for (int q = 0; q < 4; q++) {
                int ch = tid + q * 256;
                int row = ch >> 3, c16 = ch & 7;
                uint32_t sw = (uint32_t)(row * 128 + ((c16 ^ (row & 7)) << 4));
                cp_async16(a_s + sw, gA + (size_t)row * ND + c16 * 16);
                cp_async16(b_s + sw, gB + (size_t)row * ND + c16 * 16);
            }
        }
        asm volatile("cp.async.commit_group;" ::: "memory");
        int slot = it % 3;
        for (int j = tid; j < BN; j += 256)
            s_w0c[slot][j] = (lab[j0 + j] == 0) ? 1.f : 0.f;
        for (int i = tid; i < BM; i += 256)
            s_w0r[slot][i] = (lab[i0 + i] == 0) ? 1.f : 0.f;
    };

    float C[2][8][4], E[2][8][4], racc[8];
#pragma unroll
    for (int fm = 0; fm < 2; fm++)
#pragma unroll
        for (int fn = 0; fn < 8; fn++)
#pragma unroll
            for (int e = 0; e < 4; e++) C[fm][fn][e] = 0.f;

    prefetch_tile(0);

    int pj0 = 0, pr_base = 0, pdiag = 0, pslot = 0;

#pragma unroll 1
    for (int it = 0; it < cnt; it++) {
        asm volatile("cp.async.wait_group 0;" ::: "memory");
        __syncthreads();
        if (it + 1 < cnt) prefetch_tile(it + 1);

        int u = blockIdx.x + it * GRID;
        int ti, tj; tile_ij(u, ti, tj);
        const int i0 = ti * BM, j0 = tj * BN;
        const int diag = (ti == tj);
        const bool have_prev = (it > 0);
        if (have_prev) {
#pragma unroll
            for (int q = 0; q < 8; q++) racc[q] = 0.f;
        }

        uint32_t tb = sbase + (uint32_t)(it & 1) * 65536u;
#pragma unroll
        for (int chunk = 0; chunk < 8; chunk++) {
            int kb = chunk >> 2, ks = chunk & 3;
            uint32_t a_s = tb + (uint32_t)kb * 32768u;
            uint32_t b_s = a_s + 16384u;
            int c16 = ks * 2 + (lane >> 4);
            uint32_t a_frag[2][4], b_frag[4][4];
#pragma unroll
            for (int fm = 0; fm < 2; fm++) {
                int row = wm * 32 + fm * 16 + (lane & 15);
                ldsm_x4(a_frag[fm], a_s + row * 128 + ((c16 ^ (row & 7)) << 4));
            }
#pragma unroll
            for (int g = 0; g < 4; g++) {
                int row = wn * 64 + g * 16 + (lane & 15);
                ldsm_x4(b_frag[g], b_s + row * 128 + ((c16 ^ (row & 7)) << 4));
            }
#pragma unroll
            for (int fm = 0; fm < 2; fm++)
#pragma unroll
                for (int fn = 0; fn < 8; fn++) {
                    int g = fn >> 1;
                    uint32_t b0 = (fn & 1) ? b_frag[g][1] : b_frag[g][0];
                    uint32_t b1 = (fn & 1) ? b_frag[g][3] : b_frag[g][2];
                    mma16832(C[fm][fn], a_frag[fm], b0, b1);
                }
            if (have_prev)
                epi_chunk(chunk, E, racc, pslot, pj0, pr_base, pdiag, wn, rl, lane);
        }
        if (have_prev) flush_racc(racc, pr_base, lane);

        // stage C -> E, save ctx, zero C
#pragma unroll
        for (int fm = 0; fm < 2; fm++)
#pragma unroll
            for (int fn = 0; fn < 8; fn++)
#pragma unroll
                for (int e = 0; e < 4; e++) {
                    E[fm][fn][e] = C[fm][fn][e];
                    C[fm][fn][e] = 0.f;
                }
        pj0 = j0; pr_base = i0 + rl; pdiag = diag; pslot = it % 3;
    }

    // final epilogue for last tile
#pragma unroll
    for (int q = 0; q < 8; q++) racc[q] = 0.f;
#pragma unroll
    for (int chunk = 0; chunk < 8; chunk++)
        epi_chunk(chunk, E, racc, pslot, pj0, pr_base, pdiag, wn, rl, lane);
    flush_racc(racc, pr_base, lane);
}

// ---------------- pass 3: per-row margin + contrastive + final write -------
__global__ void con_final(const int* __restrict__ lab, float* __restrict__ out) {
    __shared__ double sh[8];
    __shared__ int s_last;
    int i = blockIdx.x * 256 + threadIdx.x;
    int lane = threadIdx.x & 31, wrp = threadIdx.x >> 5;
    int n0 = g_cnt, n1 = NB - n0;
    float m = g_m;

    int li = lab[i];
    float aT = g_accT[i], a0 = g_accL0[i];
    float pos = (li == 0) ? a0 : (aT - a0);
    int npos = ((li == 0) ? n0 : n1) - 1;
    int nneg = (li == 0) ? n1 : n0;
    float loc = 0.f;
    if (npos > 0 && nneg > 0)
        loc = 0.5f * (logf(aT + 1e-8f) - logf(pos));        // GAMMA*r_con
    if (li == 1)
        loc += fmaxf(m - sqrtf(g_dsq[i]), 0.f);             // BETA*r_margin
    double d = (double)loc;
#pragma unroll
    for (int o = 16; o > 0; o >>= 1)
        d += __shfl_xor_sync(0xffffffffu, d, o);
    if (lane == 0) sh[wrp] = d;
    __syncthreads();
    if (threadIdx.x == 0) {
        double s = 0.0;
#pragma unroll
        for (int w = 0; w < 8; w++) s += sh[w];
        atomicAdd(&g_mc_d, s);
        __threadfence();
        unsigned t = atomicAdd(&g_tick_cf, 1u);
        s_last = (t == (NB / 256) - 1);
        if (s_last) {
            g_tick_cf = 0u;
            out[0] = (float)((g_center_d + g_mc_d) / (double)NB);
        }
    }
}

// ---------------- launch ----------------
extern "C" void kernel_launch(void* const* d_in, const int* in_sizes, int n_in,
                              void* d_out, int out_size) {
    const float* feat = (const float*)d_in[0];
    const int*   lab  = (const int*)d_in[1];
    const float* cen  = (const float*)d_in[2];
    const float* rsig = (const float*)d_in[3];
    float* out = (float*)d_out;

    cudaFuncSetAttribute(contrast_mma,
                         cudaFuncAttributeMaxDynamicSharedMemorySize, 131072);

    row_stats<<<RSB, 256>>>(feat, lab, cen, rsig);
    contrast_mma<<<GRID, 256, 131072>>>(lab);
    con_final<<<NB / 256, 256>>>(lab, out);
}